// round 1
// baseline (speedup 1.0000x reference)
#include <cuda_runtime.h>
#include <math.h>
#include <math_constants.h>

#define BATCH 4
#define DIM 256
#define IMG 32
#define NPOS 1024
#define HEADS 8
#define DHEAD 64
#define INNER 512
#define BH 32
#define SCALE 0.125f

// ---------------- scratch (device globals; no allocations) ----------------
static __device__ float d_xt[BATCH * DIM * NPOS];        // x transposed [b][c][p]
static __device__ float d_xattn[BATCH * 2 * NPOS];       // mean/max pooled [b][2][p]
static __device__ float d_qm[BH * NPOS * 2];             // mask-q heads [bh][i][2]
static __device__ float d_km[BH * NPOS * 2];             // mask-k heads [bh][j][2]
static __device__ float d_mmax[BH * NPOS];               // mask-softmax row max
static __device__ float d_msum[BH * NPOS];               // mask-softmax row sum
static __device__ int   d_top4[BH * NPOS * 4];           // top-4 indices per row
static __device__ float d_y[BATCH * DIM * NPOS];         // depthwise/BN/GELU buffer
static __device__ float d_mean[DIM];
static __device__ float d_var[DIM];
static __device__ float d_qh[BH * NPOS * DHEAD];         // q heads [bh][i][d]
static __device__ float d_kh[BH * NPOS * DHEAD];
static __device__ float d_vh[BH * NPOS * DHEAD];
static __device__ float d_S[(size_t)BH * NPOS * NPOS];   // logits / exp scratch (128MB)
static __device__ float d_rsum[BH * NPOS];               // softmax row sums
static __device__ float d_ao[BATCH * NPOS * INNER];      // attention output [b][i][h*64+d]

// ---------------- fast exp: FMA-only (avoids MUFU bottleneck) ----------------
// exp(x) = 2^(x*log2e); n = rn(t); 2^f via degree-6 poly; exponent via bit add.
// rel err ~1e-7; inputs clamped to >= -80 (exp(-80)=1.8e-35, negligible).
__device__ __forceinline__ float fexp(float x) {
    x = fmaxf(x, -80.0f);
    float t = x * 1.44269504088896341f;
    int n = __float2int_rn(t);
    float f = t - (float)n;
    float p = 1.54035304e-4f;
    p = fmaf(p, f, 1.33335581e-3f);
    p = fmaf(p, f, 9.61812911e-3f);
    p = fmaf(p, f, 5.55041087e-2f);
    p = fmaf(p, f, 2.40226507e-1f);
    p = fmaf(p, f, 6.93147181e-1f);
    p = fmaf(p, f, 1.0f);
    return __int_as_float(__float_as_int(p) + (n << 23));
}

// mask logit: identical arithmetic everywhere it is computed
__device__ __forceinline__ float mask_logit(float qm0, float qm1, float km0, float km1) {
    return __fmul_rn(__fadd_rn(__fmul_rn(qm0, km0), __fmul_rn(qm1, km1)), SCALE);
}

// ---------------- kernel 0: transpose x[b][p][c] -> xt[b][c][p] ----------------
__global__ void k_transpose(const float* __restrict__ x) {
    __shared__ float tile[32][33];
    int b = blockIdx.z;
    int p0 = blockIdx.x * 32, c0 = blockIdx.y * 32;
    int tx = threadIdx.x, ty = threadIdx.y;  // 32 x 8
    #pragma unroll
    for (int r = 0; r < 32; r += 8)
        tile[ty + r][tx] = x[(b * NPOS + p0 + ty + r) * DIM + c0 + tx];
    __syncthreads();
    #pragma unroll
    for (int r = 0; r < 32; r += 8)
        d_xt[(b * DIM + c0 + ty + r) * NPOS + p0 + tx] = tile[tx][ty + r];
}

// ---------------- kernel 1: channel mean/max per pixel ----------------
__global__ void k_meanmax(const float* __restrict__ x) {
    int bp = blockIdx.x;  // 0..4095
    int b = bp >> 10, p = bp & 1023;
    int tid = threadIdx.x;  // 256
    float v = x[(b * NPOS + p) * DIM + tid];
    __shared__ float ss[256], sm[256];
    ss[tid] = v; sm[tid] = v;
    __syncthreads();
    for (int s = 128; s > 0; s >>= 1) {
        if (tid < s) { ss[tid] += ss[tid + s]; sm[tid] = fmaxf(sm[tid], sm[tid + s]); }
        __syncthreads();
    }
    if (tid == 0) {
        d_xattn[b * 2 * NPOS + p] = ss[0] * (1.f / 256.f);
        d_xattn[b * 2 * NPOS + NPOS + p] = sm[0];
    }
}

// ---------------- kernel 2: mask 3x3 convs (qm & km) + head layout ----------------
__global__ void k_maskconv(const float* __restrict__ qmw, const float* __restrict__ qmb,
                           const float* __restrict__ kmw, const float* __restrict__ kmb) {
    int idx = blockIdx.x * 256 + threadIdx.x;  // 4*16*1024 = 65536
    int b = idx >> 14;
    int rem = idx & 16383;
    int oc = rem >> 10;
    int p = rem & 1023;
    int py = p >> 5, px = p & 31;
    float aq = 0.f, ak = 0.f;
    #pragma unroll
    for (int ic = 0; ic < 2; ic++) {
        const float* xa = &d_xattn[(b * 2 + ic) * NPOS];
        #pragma unroll
        for (int ky = 0; ky < 3; ky++) {
            int iy = py + ky - 1;
            if ((unsigned)iy >= 32u) continue;
            #pragma unroll
            for (int kx = 0; kx < 3; kx++) {
                int ix = px + kx - 1;
                if ((unsigned)ix >= 32u) continue;
                float xv = xa[iy * 32 + ix];
                aq = fmaf(xv, qmw[((oc * 2 + ic) * 3 + ky) * 3 + kx], aq);
                ak = fmaf(xv, kmw[((oc * 2 + ic) * 3 + ky) * 3 + kx], ak);
            }
        }
    }
    aq += qmb[oc]; ak += kmb[oc];
    int h = oc >> 1, dd = oc & 1;
    d_qm[((b * HEADS + h) * NPOS + p) * 2 + dd] = aq;
    d_km[((b * HEADS + h) * NPOS + p) * 2 + dd] = ak;
}

// ---------------- kernel 3: mask softmax stats + top-4 per row ----------------
__global__ void k_masktop() {
    int row = blockIdx.x;           // 32768 rows
    int bh = row >> 10;
    int i = row & 1023;
    int tid = threadIdx.x;          // 256
    __shared__ float kms[NPOS * 2];
    for (int t = 0; t < 8; t++) { int idx = t * 256 + tid; kms[idx] = d_km[bh * NPOS * 2 + idx]; }
    __syncthreads();
    float qm0 = d_qm[(bh * NPOS + i) * 2], qm1 = d_qm[(bh * NPOS + i) * 2 + 1];
    float lv[4];
    #pragma unroll
    for (int k = 0; k < 4; k++) {
        int j = k * 256 + tid;
        lv[k] = mask_logit(qm0, qm1, kms[2 * j], kms[2 * j + 1]);
    }
    __shared__ float sval[256];
    __shared__ int sidx[256];
    int chosen[4];
    float mmax = 0.f;
    for (int sel = 0; sel < 4; sel++) {
        float bv = -CUDART_INF_F; int bj = 0x7fffffff;
        #pragma unroll
        for (int k = 0; k < 4; k++) {
            int j = k * 256 + tid;
            bool ex = false;
            for (int t = 0; t < sel; t++) ex |= (j == chosen[t]);
            float v = lv[k];
            if (!ex && (v > bv || (v == bv && j < bj))) { bv = v; bj = j; }
        }
        sval[tid] = bv; sidx[tid] = bj;
        __syncthreads();
        for (int s = 128; s > 0; s >>= 1) {
            if (tid < s) {
                float ov = sval[tid + s]; int oj = sidx[tid + s];
                if (ov > sval[tid] || (ov == sval[tid] && oj < sidx[tid])) { sval[tid] = ov; sidx[tid] = oj; }
            }
            __syncthreads();
        }
        if (sel == 0) mmax = sval[0];
        chosen[sel] = sidx[0];
        __syncthreads();
    }
    float ssum = 0.f;
    #pragma unroll
    for (int k = 0; k < 4; k++) ssum += fexp(lv[k] - mmax);
    sval[tid] = ssum;
    __syncthreads();
    for (int s = 128; s > 0; s >>= 1) { if (tid < s) sval[tid] += sval[tid + s]; __syncthreads(); }
    if (tid == 0) {
        d_mmax[row] = mmax;
        d_msum[row] = sval[0];
        for (int t = 0; t < 4; t++) d_top4[row * 4 + t] = chosen[t];
    }
}

// ---------------- depthwise 3x3 conv (per channel plane in smem) ----------------
__global__ void k_dwconv(const float* __restrict__ dw, const float* __restrict__ db) {
    int c = blockIdx.x, b = blockIdx.y;
    int tid = threadIdx.x;  // 256
    __shared__ float plane[NPOS];
    __shared__ float w[9];
    __shared__ float bias;
    const float* src = &d_xt[(b * DIM + c) * NPOS];
    for (int t = 0; t < 4; t++) plane[t * 256 + tid] = src[t * 256 + tid];
    if (tid < 9) w[tid] = dw[c * 9 + tid];
    if (tid == 9) bias = db[c];
    __syncthreads();
    float* dst = &d_y[(b * DIM + c) * NPOS];
    for (int t = 0; t < 4; t++) {
        int p = t * 256 + tid;
        int py = p >> 5, px = p & 31;
        float a = 0.f;
        #pragma unroll
        for (int ky = 0; ky < 3; ky++) {
            int iy = py + ky - 1;
            if ((unsigned)iy >= 32u) continue;
            #pragma unroll
            for (int kx = 0; kx < 3; kx++) {
                int ix = px + kx - 1;
                if ((unsigned)ix >= 32u) continue;
                a = fmaf(plane[iy * 32 + ix], w[ky * 3 + kx], a);
            }
        }
        dst[p] = a + bias;
    }
}

// ---------------- BN batch stats (per channel over b,h,w) ----------------
__global__ void k_bnstats() {
    int c = blockIdx.x;
    int tid = threadIdx.x;  // 256
    float s = 0.f, ss = 0.f;
    for (int b = 0; b < BATCH; b++) {
        const float* src = &d_y[(b * DIM + c) * NPOS];
        for (int t = 0; t < 4; t++) { float v = src[t * 256 + tid]; s += v; ss = fmaf(v, v, ss); }
    }
    __shared__ float r1[256], r2[256];
    r1[tid] = s; r2[tid] = ss;
    __syncthreads();
    for (int st = 128; st > 0; st >>= 1) {
        if (tid < st) { r1[tid] += r1[tid + st]; r2[tid] += r2[tid + st]; }
        __syncthreads();
    }
    if (tid == 0) {
        float mu = r1[0] * (1.f / 4096.f);
        float var = r2[0] * (1.f / 4096.f) - mu * mu;
        d_mean[c] = mu;
        d_var[c] = fmaxf(var, 0.f);
    }
}

// ---------------- BN normalize + exact GELU (in place) ----------------
__global__ void k_bngelu(const float* __restrict__ g, const float* __restrict__ beta) {
    int idx = blockIdx.x * 256 + threadIdx.x;  // 1M
    int c = (idx >> 10) & 255;
    float v = d_y[idx];
    float nv = (v - d_mean[c]) / sqrtf(d_var[c] + 1e-5f) * g[c] + beta[c];
    d_y[idx] = 0.5f * nv * (1.0f + erff(nv * 0.70710678118654752f));
}

// ---------------- pointwise 1x1 conv GEMM: [512 oc] x [1024 pos], K=256 ----------------
__global__ void k_pwgemm(const float* __restrict__ w, const float* __restrict__ bias, int which) {
    __shared__ float As[32][65];  // [cc][i]
    __shared__ float Ws[32][65];  // [cc][oc]
    float* out = (which == 0) ? d_qh : (which == 1) ? d_kh : d_vh;
    int b = blockIdx.z;
    int oc0 = blockIdx.y * 64;
    int i0 = blockIdx.x * 64;
    int tid = threadIdx.x;
    int ty = tid >> 4, tx = tid & 15;
    float acc[16];
    #pragma unroll
    for (int u = 0; u < 16; u++) acc[u] = 0.f;
    for (int c0 = 0; c0 < DIM; c0 += 32) {
        #pragma unroll
        for (int t = 0; t < 8; t++) {
            int idx = tid + t * 256;
            int ii = idx & 63, cc = idx >> 6;
            As[cc][ii] = d_y[(b * DIM + c0 + cc) * NPOS + i0 + ii];
        }
        #pragma unroll
        for (int t = 0; t < 8; t++) {
            int idx = tid + t * 256;
            int cc = idx & 31, o = idx >> 5;
            Ws[cc][o] = w[(oc0 + o) * DIM + c0 + cc];
        }
        __syncthreads();
        #pragma unroll
        for (int cc = 0; cc < 32; cc++) {
            float wa[4], xa[4];
            #pragma unroll
            for (int r = 0; r < 4; r++) wa[r] = Ws[cc][ty * 4 + r];
            #pragma unroll
            for (int cq = 0; cq < 4; cq++) xa[cq] = As[cc][tx * 4 + cq];
            #pragma unroll
            for (int r = 0; r < 4; r++)
                #pragma unroll
                for (int cq = 0; cq < 4; cq++)
                    acc[r * 4 + cq] = fmaf(wa[r], xa[cq], acc[r * 4 + cq]);
        }
        __syncthreads();
    }
    #pragma unroll
    for (int r = 0; r < 4; r++) {
        int oc = oc0 + ty * 4 + r;
        int h = oc >> 6, dd = oc & 63;
        float bb = bias[oc];
        #pragma unroll
        for (int cq = 0; cq < 4; cq++) {
            int ii = i0 + tx * 4 + cq;
            out[((b * HEADS + h) * NPOS + ii) * DHEAD + dd] = acc[r * 4 + cq] + bb;
        }
    }
}

// ---------------- QK^T * scale * hard_mask -> S ----------------
__global__ void k_qkmask() {
    __shared__ float Qs[64][65];  // [d][i]
    __shared__ float Ks[64][65];  // [d][j]
    __shared__ float s_qm[64][2];
    __shared__ float s_km[64][2];
    __shared__ float s_mmax[64];
    __shared__ float s_msum[64];
    __shared__ int s_top[64][4];
    int bh = blockIdx.z;
    int i0 = blockIdx.y * 64;
    int j0 = blockIdx.x * 64;
    int tid = threadIdx.x;
    int ty = tid >> 4, tx = tid & 15;
    #pragma unroll
    for (int t = 0; t < 16; t++) {
        int idx = tid + t * 256;
        int dd = idx & 63, ii = idx >> 6;
        Qs[dd][ii] = d_qh[(bh * NPOS + i0 + ii) * DHEAD + dd];
        Ks[dd][ii] = d_kh[(bh * NPOS + j0 + ii) * DHEAD + dd];
    }
    if (tid < 64) {
        int ig = bh * NPOS + i0 + tid;
        s_qm[tid][0] = d_qm[ig * 2];
        s_qm[tid][1] = d_qm[ig * 2 + 1];
        s_mmax[tid] = d_mmax[ig];
        s_msum[tid] = d_msum[ig];
        for (int t = 0; t < 4; t++) s_top[tid][t] = d_top4[ig * 4 + t];
        int jg = bh * NPOS + j0 + tid;
        s_km[tid][0] = d_km[jg * 2];
        s_km[tid][1] = d_km[jg * 2 + 1];
    }
    __syncthreads();
    float acc[16];
    #pragma unroll
    for (int u = 0; u < 16; u++) acc[u] = 0.f;
    #pragma unroll
    for (int dd = 0; dd < 64; dd++) {
        float a[4], bv[4];
        #pragma unroll
        for (int r = 0; r < 4; r++) a[r] = Qs[dd][ty * 4 + r];
        #pragma unroll
        for (int cq = 0; cq < 4; cq++) bv[cq] = Ks[dd][tx * 4 + cq];
        #pragma unroll
        for (int r = 0; r < 4; r++)
            #pragma unroll
            for (int cq = 0; cq < 4; cq++)
                acc[r * 4 + cq] = fmaf(a[r], bv[cq], acc[r * 4 + cq]);
    }
    #pragma unroll
    for (int r = 0; r < 4; r++) {
        int il = ty * 4 + r;
        float qm0 = s_qm[il][0], qm1 = s_qm[il][1];
        float mmax = s_mmax[il], msum = s_msum[il];
        int t0 = s_top[il][0], t1 = s_top[il][1], t2 = s_top[il][2], t3 = s_top[il][3];
        #pragma unroll
        for (int cq = 0; cq < 4; cq++) {
            int jl = tx * 4 + cq;
            int jg = j0 + jl;
            float ml = mask_logit(qm0, qm1, s_km[jl][0], s_km[jl][1]);
            float dprob = fexp(ml - mmax) / msum;
            float oneh = (jg == t0 || jg == t1 || jg == t2 || jg == t3) ? 1.0f : -100000.0f;
            // straight-through residue: (one_h - d) + d, rounding preserved
            float maskv = __fadd_rn(__fadd_rn(oneh, -dprob), dprob);
            float s = __fmul_rn(__fmul_rn(acc[r * 4 + cq], SCALE), maskv);
            d_S[((size_t)bh * NPOS + i0 + il) * NPOS + jg] = s;
        }
    }
}

// ---------------- row softmax: max, exp, sum (stores unnormalized exp) ----------------
__global__ void k_softmax() {
    int row = blockIdx.x;  // 32768
    int tid = threadIdx.x;  // 256
    size_t base = (size_t)row * NPOS;
    float v[4];
    float m = -CUDART_INF_F;
    #pragma unroll
    for (int k = 0; k < 4; k++) { v[k] = d_S[base + k * 256 + tid]; m = fmaxf(m, v[k]); }
    __shared__ float red[256];
    red[tid] = m;
    __syncthreads();
    for (int s = 128; s > 0; s >>= 1) { if (tid < s) red[tid] = fmaxf(red[tid], red[tid + s]); __syncthreads(); }
    m = red[0];
    __syncthreads();
    float ssum = 0.f;
    float e[4];
    #pragma unroll
    for (int k = 0; k < 4; k++) { e[k] = fexp(v[k] - m); ssum += e[k]; }
    red[tid] = ssum;
    __syncthreads();
    for (int s = 128; s > 0; s >>= 1) { if (tid < s) red[tid] += red[tid + s]; __syncthreads(); }
    if (tid == 0) d_rsum[row] = red[0];
    #pragma unroll
    for (int k = 0; k < 4; k++) d_S[base + k * 256 + tid] = e[k];
}

// ---------------- PV GEMM: out[i][d] = (E @ V)[i][d] / rowsum ----------------
__global__ void k_pv() {
    __shared__ float Es[32][65];  // [jj][i]
    __shared__ float Vs[32][65];  // [jj][d]
    int i0 = blockIdx.x * 64;
    int bh = blockIdx.y;
    int tid = threadIdx.x;
    int ty = tid >> 4, tx = tid & 15;
    float acc[16];
    #pragma unroll
    for (int u = 0; u < 16; u++) acc[u] = 0.f;
    for (int j0 = 0; j0 < NPOS; j0 += 32) {
        #pragma unroll
        for (int t = 0; t < 8; t++) {
            int idx = tid + t * 256;
            int jj = idx & 31, ii = idx >> 5;
            Es[jj][ii] = d_S[((size_t)bh * NPOS + i0 + ii) * NPOS + j0 + jj];
        }
        #pragma unroll
        for (int t = 0; t < 8; t++) {
            int idx = tid + t * 256;
            int dd = idx & 63, jj = idx >> 6;
            Vs[jj][dd] = d_vh[(bh * NPOS + j0 + jj) * DHEAD + dd];
        }
        __syncthreads();
        #pragma unroll
        for (int jj = 0; jj < 32; jj++) {
            float a[4], bv[4];
            #pragma unroll
            for (int r = 0; r < 4; r++) a[r] = Es[jj][ty * 4 + r];
            #pragma unroll
            for (int cq = 0; cq < 4; cq++) bv[cq] = Vs[jj][tx * 4 + cq];
            #pragma unroll
            for (int r = 0; r < 4; r++)
                #pragma unroll
                for (int cq = 0; cq < 4; cq++)
                    acc[r * 4 + cq] = fmaf(a[r], bv[cq], acc[r * 4 + cq]);
        }
        __syncthreads();
    }
    int b = bh >> 3, h = bh & 7;
    #pragma unroll
    for (int r = 0; r < 4; r++) {
        int ii = i0 + ty * 4 + r;
        float inv = d_rsum[bh * NPOS + ii];
        #pragma unroll
        for (int cq = 0; cq < 4; cq++) {
            int dd = tx * 4 + cq;
            d_ao[((size_t)(b * NPOS + ii)) * INNER + h * DHEAD + dd] = acc[r * 4 + cq] / inv;
        }
    }
}

// ---------------- output GEMM: [4096 x 512] @ [512 x 256]^T + bias ----------------
__global__ void k_out(const float* __restrict__ w, const float* __restrict__ ob, float* __restrict__ out) {
    __shared__ float As[32][65];  // [cc][bi]
    __shared__ float Ws[32][65];  // [cc][o]
    int o0 = blockIdx.x * 64;
    int bi0 = blockIdx.y * 64;
    int tid = threadIdx.x;
    int ty = tid >> 4, tx = tid & 15;
    float acc[16];
    #pragma unroll
    for (int u = 0; u < 16; u++) acc[u] = 0.f;
    for (int c0 = 0; c0 < INNER; c0 += 32) {
        #pragma unroll
        for (int t = 0; t < 8; t++) {
            int idx = tid + t * 256;
            int cc = idx & 31, ii = idx >> 5;
            As[cc][ii] = d_ao[(size_t)(bi0 + ii) * INNER + c0 + cc];
        }
        #pragma unroll
        for (int t = 0; t < 8; t++) {
            int idx = tid + t * 256;
            int cc = idx & 31, o = idx >> 5;
            Ws[cc][o] = w[(o0 + o) * INNER + c0 + cc];
        }
        __syncthreads();
        #pragma unroll
        for (int cc = 0; cc < 32; cc++) {
            float a[4], bv[4];
            #pragma unroll
            for (int r = 0; r < 4; r++) a[r] = As[cc][ty * 4 + r];
            #pragma unroll
            for (int cq = 0; cq < 4; cq++) bv[cq] = Ws[cc][tx * 4 + cq];
            #pragma unroll
            for (int r = 0; r < 4; r++)
                #pragma unroll
                for (int cq = 0; cq < 4; cq++)
                    acc[r * 4 + cq] = fmaf(a[r], bv[cq], acc[r * 4 + cq]);
        }
        __syncthreads();
    }
    #pragma unroll
    for (int r = 0; r < 4; r++) {
        int bi = bi0 + ty * 4 + r;
        #pragma unroll
        for (int cq = 0; cq < 4; cq++) {
            int o = o0 + tx * 4 + cq;
            out[(size_t)bi * DIM + o] = acc[r * 4 + cq] + ob[o];
        }
    }
}

// ---------------- launch ----------------
extern "C" void kernel_launch(void* const* d_in, const int* in_sizes, int n_in,
                              void* d_out, int out_size) {
    const float* x     = (const float*)d_in[0];
    const float* qd_w  = (const float*)d_in[1];
    const float* qd_b  = (const float*)d_in[2];
    const float* q_g   = (const float*)d_in[3];
    const float* q_be  = (const float*)d_in[4];
    const float* qp_w  = (const float*)d_in[5];
    const float* qp_b  = (const float*)d_in[6];
    const float* qm_w  = (const float*)d_in[7];
    const float* qm_b  = (const float*)d_in[8];
    const float* kd_w  = (const float*)d_in[9];
    const float* kd_b  = (const float*)d_in[10];
    const float* k_g   = (const float*)d_in[11];
    const float* k_be  = (const float*)d_in[12];
    const float* kp_w  = (const float*)d_in[13];
    const float* kp_b  = (const float*)d_in[14];
    const float* km_w  = (const float*)d_in[15];
    const float* km_b  = (const float*)d_in[16];
    const float* vd_w  = (const float*)d_in[17];
    const float* vd_b  = (const float*)d_in[18];
    const float* v_g   = (const float*)d_in[19];
    const float* v_be  = (const float*)d_in[20];
    const float* vp_w  = (const float*)d_in[21];
    const float* vp_b  = (const float*)d_in[22];
    const float* vm_w  = (const float*)d_in[23];
    const float* vm_b  = (const float*)d_in[24];
    const float* out_w = (const float*)d_in[25];
    const float* out_b = (const float*)d_in[26];
    float* out = (float*)d_out;

    k_transpose<<<dim3(32, 8, 4), dim3(32, 8)>>>(x);
    k_meanmax<<<4096, 256>>>(x);
    k_maskconv<<<256, 256>>>(qm_w, qm_b, km_w, km_b);
    k_masktop<<<32768, 256>>>();

    // q projection
    k_dwconv<<<dim3(256, 4), 256>>>(qd_w, qd_b);
    k_bnstats<<<256, 256>>>();
    k_bngelu<<<4096, 256>>>(q_g, q_be);
    k_pwgemm<<<dim3(16, 8, 4), 256>>>(qp_w, qp_b, 0);
    // k projection
    k_dwconv<<<dim3(256, 4), 256>>>(kd_w, kd_b);
    k_bnstats<<<256, 256>>>();
    k_bngelu<<<4096, 256>>>(k_g, k_be);
    k_pwgemm<<<dim3(16, 8, 4), 256>>>(kp_w, kp_b, 1);
    // v projection
    k_dwconv<<<dim3(256, 4), 256>>>(vd_w, vd_b);
    k_bnstats<<<256, 256>>>();
    k_bngelu<<<4096, 256>>>(v_g, v_be);
    k_pwgemm<<<dim3(16, 8, 4), 256>>>(vp_w, vp_b, 2);

    k_qkmask<<<dim3(16, 16, 32), 256>>>();
    k_softmax<<<32768, 256>>>();
    k_pv<<<dim3(16, 32), 256>>>();
    k_out<<<dim3(4, 64), 256>>>(out_w, out_b, out);
}